// round 4
// baseline (speedup 1.0000x reference)
#include <cuda_runtime.h>

#define HH   512
#define NH   32
#define LL   8192
#define CHUNKS 4            // per h-row: 4 warps, each covers 2048 l-values
#define TSTEPS 64           // l-steps per lane (stride 32) -> warp covers 2048

// Per-(h,n) constant table, 10 float2 slots:
//   0..4 : w^(2^k), k=0..4     (for the lane-power table kernel)
//   5    : w^2048
//   6    : w^4096
//   7    : w^-32
//   8    : C2 = 2*C*(w-1)/A
//   9    : (T, -Q) = (2*Re(w^32), -|w^32|^2)
#define SLOTS 10
__device__ float2 g_tab[HH * SLOTS * NH];
// Lane-power table: g_pw[h][lane][n] = w[h,n]^lane   (4 MB, L2-resident)
__device__ float2 g_pw[HH * NH * NH];

// ---------------- f32x2 packed helpers ----------------
static __device__ __forceinline__ unsigned long long pk2(float lo, float hi) {
    unsigned long long r;
    asm("mov.b64 %0, {%1, %2};" : "=l"(r) : "f"(lo), "f"(hi));
    return r;
}
static __device__ __forceinline__ void upk2(unsigned long long v, float& lo, float& hi) {
    asm("mov.b64 {%0, %1}, %2;" : "=f"(lo), "=f"(hi) : "l"(v));
}
static __device__ __forceinline__ unsigned long long mul2(unsigned long long a, unsigned long long b) {
    unsigned long long d;
    asm("mul.rn.f32x2 %0, %1, %2;" : "=l"(d) : "l"(a), "l"(b));
    return d;
}
static __device__ __forceinline__ unsigned long long add2(unsigned long long a, unsigned long long b) {
    unsigned long long d;
    asm("add.rn.f32x2 %0, %1, %2;" : "=l"(d) : "l"(a), "l"(b));
    return d;
}
static __device__ __forceinline__ unsigned long long fma2(unsigned long long a, unsigned long long b,
                                                          unsigned long long c) {
    unsigned long long d;
    asm("fma.rn.f32x2 %0, %1, %2, %3;" : "=l"(d) : "l"(a), "l"(b), "l"(c));
    return d;
}

static __device__ __forceinline__ float2 cmulf(float2 a, float2 b) {
    float2 r;
    r.x = fmaf(a.x, b.x, -(a.y * b.y));
    r.y = fmaf(a.x, b.y,  (a.y * b.x));
    return r;
}

// ---------------- Setup 1: per (h,n) constants ----------------
__global__ void s4d_setup(const float* __restrict__ Cr, const float* __restrict__ Ci,
                          const float* __restrict__ ldt, const float* __restrict__ lar,
                          const float* __restrict__ Aim) {
    int idx = blockIdx.x * blockDim.x + threadIdx.x;   // (h,n) flat
    if (idx >= HH * NH) return;
    int h = idx >> 5;
    int n = idx & 31;

    // fp32 discretization, matching reference rounding
    float dtf  = expf(ldt[h]);
    float arf  = -expf(lar[idx]);
    float aif  = Aim[idx];
    float dtar = arf * dtf;
    float dtai = aif * dtf;

    // base w = exp(dtA), fp32 (same as reference's complex64 exp)
    float er, si, co;
    er = expf(dtar);
    sincosf(dtai, &si, &co);
    float2 w = make_float2(er * co, er * si);

    // C2 = 2 * C * (w - 1) / A, fp32 like the reference
    float nr = w.x - 1.0f, ni = w.y;
    float den = arf * arf + aif * aif;
    float inv = 1.0f / den;
    float fr = (nr * arf + ni * aif) * inv;
    float fi = (ni * arf - nr * aif) * inv;
    float cr = Cr[idx], ci = Ci[idx];
    float2 C2 = make_float2(2.0f * (cr * fr - ci * fi),
                            2.0f * (cr * fi + ci * fr));

    float2* dst = g_tab + (h * SLOTS) * NH + n;        // [h][slot][n]

    // levels 0..4 by fp32 squaring; x ends at w^32
    float2 x = w;
    #pragma unroll
    for (int k = 0; k < 5; ++k) {
        dst[k * NH] = x;
        float tr = fmaf(x.x, x.x, -(x.y * x.y));
        x.y = 2.0f * x.x * x.y;
        x.x = tr;
    }
    float2 w32 = x;

    // slots 5,6: w^2048, w^4096 — fp64 phase (dtai * 2^k is exact fp32 scaling)
    {
        double s, c;
        sincos((double)dtai * 2048.0, &s, &c);
        float mag = expf(dtar * 2048.0f);   // underflow to 0 == true answer
        dst[5 * NH] = make_float2(mag * (float)c, mag * (float)s);
        sincos((double)dtai * 4096.0, &s, &c);
        float mag2 = expf(dtar * 4096.0f);
        dst[6 * NH] = make_float2(mag2 * (float)c, mag2 * (float)s);
    }

    // slot 7: w^-32 = conj(w32)/|w32|^2
    float q = fmaf(w32.x, w32.x, w32.y * w32.y);
    float qi = 1.0f / q;
    dst[7 * NH] = make_float2(w32.x * qi, -w32.y * qi);

    // slot 8: C2
    dst[8 * NH] = C2;

    // slot 9: (T, -Q)
    dst[9 * NH] = make_float2(2.0f * w32.x, -q);
}

// ---------------- Setup 2: lane-power table w^lane ----------------
__global__ void s4d_powtab() {
    __shared__ float2 sw[5][NH];
    int h = blockIdx.x;
    int t = threadIdx.x;           // 1024 threads
    int n = t & 31;
    int l = t >> 5;                // 0..31

    const float2* gt = g_tab + (h * SLOTS) * NH;
    if (t < 5 * NH) (&sw[0][0])[t] = gt[t];
    __syncthreads();

    float2 r = make_float2(1.0f, 0.0f);
    #pragma unroll
    for (int k = 0; k < 5; ++k)
        if ((l >> k) & 1) r = cmulf(r, sw[k][n]);

    g_pw[(h * NH + l) * NH + n] = r;
}

// ---------------- Main: warp per (h, quarter-row); 2-term real recurrence ----------------
__global__ void __launch_bounds__(32) s4d_main(float* __restrict__ out) {
    __shared__ float2 sC[NH];   // C2 * J(chunk)
    __shared__ float2 sD[NH];   // C2 * J * w^-32
    __shared__ float2 sT[NH];   // (T, -Q)

    int h    = blockIdx.x >> 2;
    int c    = blockIdx.x & 3;
    int lane = threadIdx.x;

    // Cooperative per-mode init: lane m handles mode m
    {
        const float2* gt = g_tab + (h * SLOTS) * NH + lane;
        float2 w2k  = gt[5 * NH];
        float2 w4k  = gt[6 * NH];
        float2 wm32 = gt[7 * NH];
        float2 C2   = gt[8 * NH];
        float2 tq   = gt[9 * NH];
        float2 J = make_float2(1.0f, 0.0f);
        if (c & 1) J = w2k;
        if (c & 2) J = cmulf(J, w4k);
        float2 C2J = cmulf(C2, J);
        sC[lane] = C2J;
        sD[lane] = cmulf(C2J, wm32);
        sT[lane] = tq;
    }
    __syncwarp();

    // Per-thread state: 16 mode-pairs packed in f32x2
    unsigned long long cur[16], prv[16], T2[16], Qn[16];

    const float4* pw4 = (const float4*)(g_pw + (h * NH + lane) * NH);
    #pragma unroll
    for (int j = 0; j < 16; ++j) {
        int m0 = 2 * j, m1 = 2 * j + 1;
        float4 v = pw4[j];                       // w[m0]^lane, w[m1]^lane
        float2 wl0 = make_float2(v.x, v.y);
        float2 wl1 = make_float2(v.z, v.w);
        float2 pa = cmulf(wl0, sC[m0]);
        float2 pb = cmulf(wl1, sC[m1]);
        float2 qa = cmulf(wl0, sD[m0]);
        float2 qb = cmulf(wl1, sD[m1]);
        cur[j] = pk2(pa.x, pb.x);
        prv[j] = pk2(qa.x, qb.x);
        T2[j]  = pk2(sT[m0].x, sT[m1].x);        //  T  = 2 Re(w^32)
        Qn[j]  = pk2(sT[m0].y, sT[m1].y);        // -Q  = -|w^32|^2
    }

    float* op = out + h * LL + c * (LL / CHUNKS) + lane;

    #pragma unroll 2
    for (int t = 0; t < TSTEPS; t += 2) {
        // ---- emit sum(cur) at l = t ----
        {
            unsigned long long s8[8];
            #pragma unroll
            for (int j = 0; j < 8; ++j) s8[j] = add2(cur[2 * j], cur[2 * j + 1]);
            unsigned long long s4a = add2(s8[0], s8[1]);
            unsigned long long s4b = add2(s8[2], s8[3]);
            unsigned long long s4c = add2(s8[4], s8[5]);
            unsigned long long s4d = add2(s8[6], s8[7]);
            unsigned long long acc = add2(add2(s4a, s4b), add2(s4c, s4d));
            float lo, hi;
            upk2(acc, lo, hi);
            __stcs(op + t * 32, lo + hi);
        }
        // advance: prv <- T*cur - Q*prv
        #pragma unroll
        for (int j = 0; j < 16; ++j)
            prv[j] = fma2(T2[j], cur[j], mul2(Qn[j], prv[j]));

        // ---- emit sum(prv) at l = t+1 ----
        {
            unsigned long long s8[8];
            #pragma unroll
            for (int j = 0; j < 8; ++j) s8[j] = add2(prv[2 * j], prv[2 * j + 1]);
            unsigned long long s4a = add2(s8[0], s8[1]);
            unsigned long long s4b = add2(s8[2], s8[3]);
            unsigned long long s4c = add2(s8[4], s8[5]);
            unsigned long long s4d = add2(s8[6], s8[7]);
            unsigned long long acc = add2(add2(s4a, s4b), add2(s4c, s4d));
            float lo, hi;
            upk2(acc, lo, hi);
            __stcs(op + (t + 1) * 32, lo + hi);
        }
        // advance: cur <- T*prv - Q*cur
        #pragma unroll
        for (int j = 0; j < 16; ++j)
            cur[j] = fma2(T2[j], prv[j], mul2(Qn[j], cur[j]));
    }
}

extern "C" void kernel_launch(void* const* d_in, const int* in_sizes, int n_in,
                              void* d_out, int out_size) {
    const float* C_real     = (const float*)d_in[0];
    const float* C_imag     = (const float*)d_in[1];
    const float* log_dt     = (const float*)d_in[2];
    const float* log_a_real = (const float*)d_in[3];
    const float* A_imag     = (const float*)d_in[4];
    float* out = (float*)d_out;

    s4d_setup<<<(HH * NH + 255) / 256, 256>>>(C_real, C_imag, log_dt, log_a_real, A_imag);
    s4d_powtab<<<HH, NH * NH>>>();
    s4d_main<<<HH * CHUNKS, 32>>>(out);
}

// round 5
// speedup vs baseline: 1.3265x; 1.3265x over previous
#include <cuda_runtime.h>
#include <math_constants.h>

#define HH   512
#define NH   32
#define LL   8192
#define CHUNKS 4            // per h-row: 4 warps, each covers 2048 l-values
#define TSTEPS 64           // l-steps per lane (stride 32) -> warp covers 2048

// Per-(h,n) constant table, 5 float2 slots: [h][slot][n]
//   0 : w^2048
//   1 : w^4096
//   2 : w^-32
//   3 : C2 = 2*C*(w-1)/A
//   4 : (T, -Q) = (2*Re(w^32), -|w^32|^2)
#define SLOTS 5
__device__ float2 g_tab[HH * SLOTS * NH];
// Lane-power table, main-coalesced layout:
// g_pw4[h][j][lane] = (w_{2j}^lane, w_{2j+1}^lane)   (4 MB, L2-resident)
__device__ float4 g_pw4[HH * 16 * NH];

// ---------------- f32x2 packed helpers ----------------
static __device__ __forceinline__ unsigned long long pk2(float lo, float hi) {
    unsigned long long r;
    asm("mov.b64 %0, {%1, %2};" : "=l"(r) : "f"(lo), "f"(hi));
    return r;
}
static __device__ __forceinline__ void upk2(unsigned long long v, float& lo, float& hi) {
    asm("mov.b64 {%0, %1}, %2;" : "=f"(lo), "=f"(hi) : "l"(v));
}
static __device__ __forceinline__ unsigned long long mul2(unsigned long long a, unsigned long long b) {
    unsigned long long d;
    asm("mul.rn.f32x2 %0, %1, %2;" : "=l"(d) : "l"(a), "l"(b));
    return d;
}
static __device__ __forceinline__ unsigned long long add2(unsigned long long a, unsigned long long b) {
    unsigned long long d;
    asm("add.rn.f32x2 %0, %1, %2;" : "=l"(d) : "l"(a), "l"(b));
    return d;
}
static __device__ __forceinline__ unsigned long long fma2(unsigned long long a, unsigned long long b,
                                                          unsigned long long c) {
    unsigned long long d;
    asm("fma.rn.f32x2 %0, %1, %2, %3;" : "=l"(d) : "l"(a), "l"(b), "l"(c));
    return d;
}

static __device__ __forceinline__ float2 cmulf(float2 a, float2 b) {
    float2 r;
    r.x = fmaf(a.x, b.x, -(a.y * b.y));
    r.y = fmaf(a.x, b.y,  (a.y * b.x));
    return r;
}

// w^p for large p without fp64 transcendentals:
// phase = dtai * p ; reduce u = phase/pi mod 2 via double mults, then sincospif
static __device__ __forceinline__ float2 bigpow(float dtar, float dtai, float p) {
    double u = (double)dtai * (double)p * (1.0 / CUDART_PI);
    double f = u - 2.0 * rint(u * 0.5);          // in [-1, 1]
    float s, c;
    sincospif((float)f, &s, &c);
    float mag = expf(dtar * p);                  // underflow to 0 == true answer
    return make_float2(mag * c, mag * s);
}

// ---------------- Fused setup: constants + lane-power table ----------------
// grid = HH, block = 512.  Stage 1: threads 0..31 (n) compute per-(h,n) constants.
// Stage 2: threads (l = t>>4, j = t&15) build g_pw4[h][j][l].
__global__ void __launch_bounds__(512) s4d_setup(const float* __restrict__ Cr,
                                                 const float* __restrict__ Ci,
                                                 const float* __restrict__ ldt,
                                                 const float* __restrict__ lar,
                                                 const float* __restrict__ Aim) {
    __shared__ float2 lev[5][NH];     // w^(2^k), k=0..4

    int h = blockIdx.x;
    int t = threadIdx.x;

    if (t < NH) {
        int n = t;
        int idx = h * NH + n;

        float dtf  = expf(ldt[h]);
        float arf  = -expf(lar[idx]);
        float aif  = Aim[idx];
        float dtar = arf * dtf;
        float dtai = aif * dtf;

        // base w = exp(dtA), fp32 (matches reference complex64 exp)
        float er, si, co;
        er = expf(dtar);
        sincosf(dtai, &si, &co);
        float2 w = make_float2(er * co, er * si);

        // C2 = 2 * C * (w - 1) / A, fp32 like the reference
        float nr = w.x - 1.0f, ni = w.y;
        float den = arf * arf + aif * aif;
        float inv = 1.0f / den;
        float fr = (nr * arf + ni * aif) * inv;
        float fi = (ni * arf - nr * aif) * inv;
        float cr = Cr[idx], ci = Ci[idx];
        float2 C2 = make_float2(2.0f * (cr * fr - ci * fi),
                                2.0f * (cr * fi + ci * fr));

        // levels 0..4 by fp32 squaring; ends with w32
        float2 x = w;
        #pragma unroll
        for (int k = 0; k < 5; ++k) {
            lev[k][n] = x;
            float tr = fmaf(x.x, x.x, -(x.y * x.y));
            x.y = 2.0f * x.x * x.y;
            x.x = tr;
        }
        float2 w32 = x;   // wait: x is now w^32 after 5 squarings? k=0 stores w, then squares.
        // after loop x = w^32 (stored levels w^1..w^16). Correct.

        float2* dst = g_tab + (h * SLOTS) * NH + n;
        dst[0 * NH] = bigpow(dtar, dtai, 2048.0f);
        dst[1 * NH] = bigpow(dtar, dtai, 4096.0f);

        float q  = fmaf(w32.x, w32.x, w32.y * w32.y);
        float qi = 1.0f / q;
        dst[2 * NH] = make_float2(w32.x * qi, -w32.y * qi);   // w^-32
        dst[3 * NH] = C2;
        dst[4 * NH] = make_float2(2.0f * w32.x, -q);          // (T, -Q)
    }
    __syncthreads();

    // Stage 2: lane-power table
    int l = t >> 4;          // 0..31
    int j = t & 15;          // mode pair
    int m0 = 2 * j, m1 = 2 * j + 1;
    float2 a = make_float2(1.0f, 0.0f);
    float2 b = make_float2(1.0f, 0.0f);
    #pragma unroll
    for (int k = 0; k < 5; ++k) {
        if ((l >> k) & 1) {
            a = cmulf(a, lev[k][m0]);
            b = cmulf(b, lev[k][m1]);
        }
    }
    g_pw4[(h * 16 + j) * NH + l] = make_float4(a.x, a.y, b.x, b.y);
}

// ---------------- Main: block per h (4 warps = 4 chunks); 2-term real recurrence ----------------
__global__ void __launch_bounds__(128) s4d_main(float* __restrict__ out) {
    __shared__ float2 sC[CHUNKS][NH];   // C2 * J(chunk)
    __shared__ float2 sD[CHUNKS][NH];   // C2 * J * w^-32
    __shared__ float2 sT[CHUNKS][NH];   // (T, -Q)

    int h    = blockIdx.x;
    int c    = threadIdx.x >> 5;        // warp = chunk
    int lane = threadIdx.x & 31;

    // Cooperative per-mode init: lane m handles mode m (per warp)
    {
        const float2* gt = g_tab + (h * SLOTS) * NH + lane;
        float2 w2k  = gt[0 * NH];
        float2 w4k  = gt[1 * NH];
        float2 wm32 = gt[2 * NH];
        float2 C2   = gt[3 * NH];
        float2 tq   = gt[4 * NH];
        float2 J = make_float2(1.0f, 0.0f);
        if (c & 1) J = w2k;
        if (c & 2) J = cmulf(J, w4k);
        float2 C2J = cmulf(C2, J);
        sC[c][lane] = C2J;
        sD[c][lane] = cmulf(C2J, wm32);
        sT[c][lane] = tq;
    }
    __syncwarp();

    // Per-thread state: 16 mode-pairs packed in f32x2
    unsigned long long cur[16], prv[16], T2[16], Qn[16];

    const float4* pw = g_pw4 + h * 16 * NH + lane;
    #pragma unroll
    for (int j = 0; j < 16; ++j) {
        int m0 = 2 * j, m1 = 2 * j + 1;
        float4 v = pw[j * NH];                   // coalesced across lanes
        float2 wl0 = make_float2(v.x, v.y);
        float2 wl1 = make_float2(v.z, v.w);
        float2 pa = cmulf(wl0, sC[c][m0]);
        float2 pb = cmulf(wl1, sC[c][m1]);
        float2 qa = cmulf(wl0, sD[c][m0]);
        float2 qb = cmulf(wl1, sD[c][m1]);
        cur[j] = pk2(pa.x, pb.x);
        prv[j] = pk2(qa.x, qb.x);
        T2[j]  = pk2(sT[c][m0].x, sT[c][m1].x);  //  T  = 2 Re(w^32)
        Qn[j]  = pk2(sT[c][m0].y, sT[c][m1].y);  // -Q  = -|w^32|^2
    }

    float* op = out + h * LL + c * (LL / CHUNKS) + lane;

    #pragma unroll 2
    for (int t = 0; t < TSTEPS; t += 2) {
        // ---- emit sum(cur) at l = t ----
        {
            unsigned long long s8[8];
            #pragma unroll
            for (int j = 0; j < 8; ++j) s8[j] = add2(cur[2 * j], cur[2 * j + 1]);
            unsigned long long s4a = add2(s8[0], s8[1]);
            unsigned long long s4b = add2(s8[2], s8[3]);
            unsigned long long s4c = add2(s8[4], s8[5]);
            unsigned long long s4d = add2(s8[6], s8[7]);
            unsigned long long acc = add2(add2(s4a, s4b), add2(s4c, s4d));
            float lo, hi;
            upk2(acc, lo, hi);
            __stcs(op + t * 32, lo + hi);
        }
        // advance: prv <- T*cur - Q*prv
        #pragma unroll
        for (int j = 0; j < 16; ++j)
            prv[j] = fma2(T2[j], cur[j], mul2(Qn[j], prv[j]));

        // ---- emit sum(prv) at l = t+1 ----
        {
            unsigned long long s8[8];
            #pragma unroll
            for (int j = 0; j < 8; ++j) s8[j] = add2(prv[2 * j], prv[2 * j + 1]);
            unsigned long long s4a = add2(s8[0], s8[1]);
            unsigned long long s4b = add2(s8[2], s8[3]);
            unsigned long long s4c = add2(s8[4], s8[5]);
            unsigned long long s4d = add2(s8[6], s8[7]);
            unsigned long long acc = add2(add2(s4a, s4b), add2(s4c, s4d));
            float lo, hi;
            upk2(acc, lo, hi);
            __stcs(op + (t + 1) * 32, lo + hi);
        }
        // advance: cur <- T*prv - Q*cur
        #pragma unroll
        for (int j = 0; j < 16; ++j)
            cur[j] = fma2(T2[j], prv[j], mul2(Qn[j], cur[j]));
    }
}

extern "C" void kernel_launch(void* const* d_in, const int* in_sizes, int n_in,
                              void* d_out, int out_size) {
    const float* C_real     = (const float*)d_in[0];
    const float* C_imag     = (const float*)d_in[1];
    const float* log_dt     = (const float*)d_in[2];
    const float* log_a_real = (const float*)d_in[3];
    const float* A_imag     = (const float*)d_in[4];
    float* out = (float*)d_out;

    s4d_setup<<<HH, 512>>>(C_real, C_imag, log_dt, log_a_real, A_imag);
    s4d_main<<<HH, 128>>>(out);
}